// round 1
// baseline (speedup 1.0000x reference)
#include <cuda_runtime.h>
#include <cstdint>

#define HIDDEN 128
#define MAX_NODES 50000

// Scratch for layer-1 output (learn1). 50000*128 fp32 = 25.6 MB.
__device__ float g_learn1[MAX_NODES * HIDDEN];

// ---------------------------------------------------------------------------
// Kernel 1: initialize accumulators with their bias rows.
//   learn1[n][h] = bias[0][h];  out[n][h] = bias[1][h]
// Operates in float4 units: total = n_nodes*HIDDEN/4 float4s, 32 float4/row.
// ---------------------------------------------------------------------------
__global__ void init_bias_kernel(float4* __restrict__ learn1,
                                 float4* __restrict__ out,
                                 const float4* __restrict__ bias, // [2][32] float4
                                 int total4) {
    int i = blockIdx.x * blockDim.x + threadIdx.x;
    if (i >= total4) return;
    int h4 = i & 31;                 // float4-column within the 128-wide row
    learn1[i] = bias[h4];            // bias row 0
    out[i]    = bias[32 + h4];       // bias row 1
}

// ---------------------------------------------------------------------------
// Kernel 2: COO SpMM scatter:  y[row[e]] += val[e] * x[col[e]]
// One warp per edge. Lane l handles float4 #l of the 128-float row.
// Gather is a coalesced 512B row read (L2-resident: 25.6MB << 126MB L2).
// Scatter uses red.global.add.v4.f32 (128-bit no-return atomic, sm_90+).
// ---------------------------------------------------------------------------
__global__ void spmm_kernel(const float* __restrict__ x,
                            float* __restrict__ y,
                            const int* __restrict__ row,
                            const int* __restrict__ col,
                            const float* __restrict__ val,
                            int n_edges) {
    int gtid = blockIdx.x * blockDim.x + threadIdx.x;
    int e = gtid >> 5;
    if (e >= n_edges) return;
    int lane = threadIdx.x & 31;

    int r = __ldg(row + e);
    int c = __ldg(col + e);
    float v = __ldg(val + e);

    const float4* src = reinterpret_cast<const float4*>(x) + (size_t)c * 32 + lane;
    float4* dst       = reinterpret_cast<float4*>(y)       + (size_t)r * 32 + lane;

    float4 m = __ldg(src);
    m.x *= v; m.y *= v; m.z *= v; m.w *= v;

    asm volatile("red.global.add.v4.f32 [%0], {%1,%2,%3,%4};"
                 :: "l"(dst), "f"(m.x), "f"(m.y), "f"(m.z), "f"(m.w)
                 : "memory");
}

// ---------------------------------------------------------------------------
// Kernel 3: final residual average: out = (fea + learn1 + out) / 3
// ---------------------------------------------------------------------------
__global__ void final_kernel(const float4* __restrict__ fea,
                             const float4* __restrict__ learn1,
                             float4* __restrict__ out,
                             int total4) {
    int i = blockIdx.x * blockDim.x + threadIdx.x;
    if (i >= total4) return;
    const float inv3 = 1.0f / 3.0f;
    float4 a = __ldg(fea + i);
    float4 b = __ldg(learn1 + i);
    float4 c = out[i];
    float4 r;
    r.x = (a.x + b.x + c.x) * inv3;
    r.y = (a.y + b.y + c.y) * inv3;
    r.z = (a.z + b.z + c.z) * inv3;
    r.w = (a.w + b.w + c.w) * inv3;
    out[i] = r;
}

extern "C" void kernel_launch(void* const* d_in, const int* in_sizes, int n_in,
                              void* d_out, int out_size) {
    const float* fea     = (const float*)d_in[0];   // [N, 128]
    const int*   adj_row = (const int*)  d_in[1];   // [E]
    const int*   adj_col = (const int*)  d_in[2];   // [E]
    const float* adj_val = (const float*)d_in[3];   // [E]
    const float* bias    = (const float*)d_in[4];   // [2, 128]

    int n_edges = in_sizes[1];
    int n_nodes = in_sizes[0] / HIDDEN;
    int total4  = n_nodes * (HIDDEN / 4);           // float4 count

    float* learn1 = nullptr;
    cudaGetSymbolAddress((void**)&learn1, g_learn1);
    float* out = (float*)d_out;

    // 1) learn1 = bias0 (broadcast), out = bias1 (broadcast)
    {
        int tpb = 256;
        int blocks = (total4 + tpb - 1) / tpb;
        init_bias_kernel<<<blocks, tpb>>>((float4*)learn1, (float4*)out,
                                          (const float4*)bias, total4);
    }

    // 2) learn1 += spmm(fea)   — warp per edge
    {
        int tpb = 256;                       // 8 warps/block
        int warps_needed = n_edges;
        int blocks = (warps_needed * 32 + tpb - 1) / tpb;
        spmm_kernel<<<blocks, tpb>>>(fea, learn1, adj_row, adj_col, adj_val, n_edges);
    }

    // 3) out += spmm(learn1)
    {
        int tpb = 256;
        int blocks = (n_edges * 32 + tpb - 1) / tpb;
        spmm_kernel<<<blocks, tpb>>>(learn1, out, adj_row, adj_col, adj_val, n_edges);
    }

    // 4) out = (fea + learn1 + out) / 3
    {
        int tpb = 256;
        int blocks = (total4 + tpb - 1) / tpb;
        final_kernel<<<blocks, tpb>>>((const float4*)fea, (const float4*)learn1,
                                      (float4*)out, total4);
    }
}